// round 12
// baseline (speedup 1.0000x reference)
#include <cuda_runtime.h>
#include <cstdint>

// Problem constants: B=96, N_NODE=512, D=128, n_steps=5
#define NB 96
#define NN 512
#define ND 128
#define NROWS (NB * NN)          // 49152
#define NSTEPS 5

// Scratch (allocation-free rule: __device__ globals)
__device__ float g_Whi[7 * ND * ND];            // tf32-hi of weights [w][j][k]
__device__ float g_Wlo[7 * ND * ND];            // tf32-lo
__device__ float g_hp[(size_t)NROWS * ND];      // fp32 [node][feat] = h @ Wp^T
__device__ float g_neigh[(size_t)NROWS * ND];   // fp32 agg = mask @ hp  (NO bias)
__device__ float g_cvec[3 * ND];                // cz, cr, ch  (bias folded per gate)
// weight order: 0=Wz 1=Uz 2=Wr 3=Ur 4=Wh 5=Uh 6=Wp

typedef unsigned long long ull;

// ---------------------------------------------------------------------------
// Common helpers
// ---------------------------------------------------------------------------
__device__ __forceinline__ uint32_t s2u(const void* p) {
    uint32_t a;
    asm("{ .reg .u64 t; cvta.to.shared.u64 t, %1; cvt.u32.u64 %0, t; }" : "=r"(a) : "l"(p));
    return a;
}
__device__ __forceinline__ void cp16(float* dst, const float* src) {
    asm volatile("cp.async.cg.shared.global [%0], [%1], 16;" :: "r"(s2u(dst)), "l"(src));
}
#define CP_COMMIT() asm volatile("cp.async.commit_group;")
#define CP_WAIT(n)  asm volatile("cp.async.wait_group %0;" :: "n"(n))
__device__ __forceinline__ float sigm(float x) { return 1.0f / (1.0f + __expf(-x)); }

// ---- tf32 split: x = hi + lo + e, |e| ~ 2^-24 |x| ----
__device__ __forceinline__ void split_tf32(float x, uint32_t& hi, uint32_t& lo) {
    asm("cvt.rna.tf32.f32 %0, %1;" : "=r"(hi) : "f"(x));
    float r = x - __uint_as_float(hi);
    asm("cvt.rna.tf32.f32 %0, %1;" : "=r"(lo) : "f"(r));
}
__device__ __forceinline__ void mma8(float c[4], const uint32_t a[4], const uint32_t b[2]) {
    asm volatile("mma.sync.aligned.m16n8k8.row.col.f32.tf32.tf32.f32 "
        "{%0,%1,%2,%3},{%4,%5,%6,%7},{%8,%9},{%0,%1,%2,%3};"
        : "+f"(c[0]), "+f"(c[1]), "+f"(c[2]), "+f"(c[3])
        : "r"(a[0]), "r"(a[1]), "r"(a[2]), "r"(a[3]), "r"(b[0]), "r"(b[1]));
}
template<int MT, int NT>
__device__ __forceinline__ void zaccf(float a[MT][NT][4]) {
#pragma unroll
    for (int i = 0; i < MT; i++)
#pragma unroll
        for (int j = 0; j < NT; j++)
#pragma unroll
            for (int e = 0; e < 4; e++) a[i][j][e] = 0.0f;
}

// 4xTF32 warp GEMM: C[m,n] += A[m][k]*B[n][k]; A fp32 (split on fly),
// B pre-split hi/lo. Full product (ah+al)(bh+bl) — 4 MMAs per tile pair.
template<int MT, int NT, int K, int LDA, int LDB>
__device__ __forceinline__ void wgemm4(const float* __restrict__ sA,
                                       const float* __restrict__ sBh,
                                       const float* __restrict__ sBl,
                                       int mBase, int nBase, float acc[MT][NT][4]) {
    int lane = threadIdx.x & 31;
    int q = lane >> 2, rr = lane & 3;
#pragma unroll
    for (int k0 = 0; k0 < K; k0 += 8) {
        uint32_t ah[MT][4], al[MT][4];
#pragma unroll
        for (int mt = 0; mt < MT; mt++) {
            const float* p = sA + (mBase + mt * 16 + q) * LDA + k0 + rr;
            split_tf32(p[0],           ah[mt][0], al[mt][0]);
            split_tf32(p[8 * LDA],     ah[mt][1], al[mt][1]);
            split_tf32(p[4],           ah[mt][2], al[mt][2]);
            split_tf32(p[8 * LDA + 4], ah[mt][3], al[mt][3]);
        }
        uint32_t bh[NT][2], bl[NT][2];
#pragma unroll
        for (int nt = 0; nt < NT; nt++) {
            const float* ph = sBh + (nBase + nt * 8 + q) * LDB + k0 + rr;
            const float* pl = sBl + (nBase + nt * 8 + q) * LDB + k0 + rr;
            bh[nt][0] = __float_as_uint(ph[0]); bh[nt][1] = __float_as_uint(ph[4]);
            bl[nt][0] = __float_as_uint(pl[0]); bl[nt][1] = __float_as_uint(pl[4]);
        }
#pragma unroll
        for (int mt = 0; mt < MT; mt++)
#pragma unroll
            for (int nt = 0; nt < NT; nt++) {
                mma8(acc[mt][nt], ah[mt], bh[nt]);
                mma8(acc[mt][nt], al[mt], bh[nt]);
                mma8(acc[mt][nt], ah[mt], bl[nt]);
                mma8(acc[mt][nt], al[mt], bl[nt]);
            }
    }
}

// ---- fp32 f32x2 SIMT micro-kernel (proven R8 path, for the mask GEMM) ----
__device__ __forceinline__ ull pack2(float lo, float hi) {
    ull r; asm("mov.b64 %0, {%1,%2};" : "=l"(r) : "f"(lo), "f"(hi)); return r;
}
__device__ __forceinline__ void fma2(ull& d, ull a, ull b) {
    asm("fma.rn.f32x2 %0, %1, %2, %0;" : "+l"(d) : "l"(a), "l"(b));
}
__device__ __forceinline__ void unpack2(ull v, float& lo, float& hi) {
    asm("mov.b64 {%0,%1}, %2;" : "=f"(lo), "=f"(hi) : "l"(v));
}
template <int LDA>
__device__ __forceinline__ void mma_half(const float* __restrict__ sX,
                                         const float* __restrict__ sW,
                                         int kbase, int r0, int c0, ull acc[8][4]) {
#pragma unroll 2
    for (int k = 0; k < 64; k += 4) {
        float4 a[8];
#pragma unroll
        for (int i = 0; i < 8; i++)
            a[i] = *(const float4*)(sX + (r0 + i) * LDA + kbase + k);
#pragma unroll
        for (int kk = 0; kk < 4; kk++) {
            const float* wr = sW + (k + kk) * 132;
            float4 w0 = *(const float4*)(wr + c0);
            float4 w1 = *(const float4*)(wr + c0 + 64);
            ull wp0 = pack2(w0.x, w0.y), wp1 = pack2(w0.z, w0.w);
            ull wp2 = pack2(w1.x, w1.y), wp3 = pack2(w1.z, w1.w);
#pragma unroll
            for (int i = 0; i < 8; i++) {
                float e = (kk == 0) ? a[i].x : (kk == 1) ? a[i].y : (kk == 2) ? a[i].z : a[i].w;
                ull ap = pack2(e, e);
                fma2(acc[i][0], ap, wp0); fma2(acc[i][1], ap, wp1);
                fma2(acc[i][2], ap, wp2); fma2(acc[i][3], ap, wp3);
            }
        }
    }
}
__device__ __forceinline__ void zacc8(ull acc[8][4]) {
#pragma unroll
    for (int i = 0; i < 8; i++)
#pragma unroll
        for (int p = 0; p < 4; p++) acc[i][p] = 0ull;
}
__device__ __forceinline__ void row_f8(const ull a[4], float o[8]) {
    unpack2(a[0], o[0], o[1]); unpack2(a[1], o[2], o[3]);
    unpack2(a[2], o[4], o[5]); unpack2(a[3], o[6], o[7]);
}
__device__ __forceinline__ int colof(int c0, int j) { return (j < 4) ? (c0 + j) : (c0 + 60 + j); }

// ---------------------------------------------------------------------------
// Kernel 0: split weights into tf32 hi/lo; compute folded gate constants
//   c_g[f] = 512 * sum_k Wg[f][k]*Wp_b[k] + Wg_b[f] + Ug_b[f]
// ---------------------------------------------------------------------------
__global__ void prep_kernel(const float* __restrict__ Wz, const float* __restrict__ Uz,
                            const float* __restrict__ Wr, const float* __restrict__ Ur,
                            const float* __restrict__ Wh, const float* __restrict__ Uh,
                            const float* __restrict__ Wp,
                            const float* __restrict__ Wz_b, const float* __restrict__ Uz_b,
                            const float* __restrict__ Wr_b, const float* __restrict__ Ur_b,
                            const float* __restrict__ Wh_b, const float* __restrict__ Uh_b,
                            const float* __restrict__ Wp_b) {
    int b = blockIdx.x;
    if (b < 7) {
        const float* src = (b == 0) ? Wz : (b == 1) ? Uz : (b == 2) ? Wr :
                           (b == 3) ? Ur : (b == 4) ? Wh : (b == 5) ? Uh : Wp;
        for (int idx = threadIdx.x; idx < ND * ND; idx += blockDim.x) {
            uint32_t hi, lo;
            split_tf32(src[idx], hi, lo);
            g_Whi[b * ND * ND + idx] = __uint_as_float(hi);
            g_Wlo[b * ND * ND + idx] = __uint_as_float(lo);
        }
    } else {
        int g = b - 7;   // 0=z, 1=r, 2=h
        const float* W  = (g == 0) ? Wz : (g == 1) ? Wr : Wh;
        const float* b1 = (g == 0) ? Wz_b : (g == 1) ? Wr_b : Wh_b;
        const float* b2 = (g == 0) ? Uz_b : (g == 1) ? Ur_b : Uh_b;
        int f = threadIdx.x;
        if (f < ND) {
            float s = 0.0f;
            for (int k = 0; k < ND; k++) s += W[f * ND + k] * Wp_b[k];
            g_cvec[g * ND + f] = 512.0f * s + b1[f] + b2[f];
        }
    }
}

// ---------------------------------------------------------------------------
// Kernel 1 (once): hp0 = h0 @ Wp^T via 4xtf32. 256 thr, 64-node tiles.
// ---------------------------------------------------------------------------
#define XW_SMEM ((64 * 132 + 2 * 128 * 132) * 4)   // 168960
__global__ void __launch_bounds__(256) xw_t(const float* __restrict__ h0) {
    extern __shared__ float sm[];
    float* sX  = sm;                 // [64][132] fp32
    float* sWh = sm + 64 * 132;      // [128][132]
    float* sWl = sWh + 128 * 132;
    int tid = threadIdx.x, wid = tid >> 5, lane = tid & 31;
    int node0 = blockIdx.x * 64;
#pragma unroll
    for (int t = 0; t < 8; t++) {
        int f = tid + t * 256; int r = f >> 5, c = (f & 31) << 2;
        cp16(sX + r * 132 + c, h0 + (size_t)(node0 + r) * ND + c);
    }
#pragma unroll
    for (int t = 0; t < 16; t++) {
        int f = tid + t * 256; int r = f >> 5, c = (f & 31) << 2;
        cp16(sWh + r * 132 + c, g_Whi + 6 * ND * ND + r * ND + c);
        cp16(sWl + r * 132 + c, g_Wlo + 6 * ND * ND + r * ND + c);
    }
    CP_COMMIT();
    CP_WAIT(0); __syncthreads();
    int gm = (wid & 1) * 32, gn = (wid >> 1) * 32;    // 64 nodes x 128 feats
    float acc[2][4][4]; zaccf<2, 4>(acc);
    wgemm4<2, 4, 128, 132, 132>(sX, sWh, sWl, gm, gn, acc);
#pragma unroll
    for (int mt = 0; mt < 2; mt++)
#pragma unroll
        for (int nt = 0; nt < 4; nt++)
#pragma unroll
            for (int e = 0; e < 4; e++) {
                int row = gm + mt * 16 + (lane >> 2) + ((e >> 1) << 3);
                int col = gn + nt * 8 + ((lane & 3) << 1) + (e & 1);
                g_hp[(size_t)(node0 + row) * ND + col] = acc[mt][nt][e];
            }
}

// ---------------------------------------------------------------------------
// Kernel 2: agg[b] = mask[b] @ hp[b]  (exact fp32 SIMT, NO bias).
// 128x128 tile, r8c8, K=512 in 8 chunks of 64, cp.async double-buffered.
// ---------------------------------------------------------------------------
#define MG_SMEM ((2 * 128 * 68 + 2 * 64 * 132) * 4)   // 137216
__global__ void __launch_bounds__(256) maskgemm_kernel(const float* __restrict__ mask) {
    extern __shared__ float sm[];
    float* sA[2] = { sm, sm + 128 * 68 };
    float* sB[2] = { sm + 2 * 128 * 68, sm + 2 * 128 * 68 + 64 * 132 };
    int b = blockIdx.y;
    int row0g = blockIdx.x * 128;
    int tid = threadIdx.x;
    int tx = tid & 15, ty = tid >> 4;
    int c0 = tx * 4, r0 = ty * 8;
    const float* mrow = mask + ((size_t)b * NN + row0g) * NN;
    const float* hpb  = g_hp + (size_t)b * NN * ND;

    auto loadChunk = [&](int buf, int k0) {
#pragma unroll
        for (int t = 0; t < 8; t++) {          // mask 128x64
            int f = tid + t * 256;
            int r = f >> 4, kq = (f & 15) << 2;
            cp16(sA[buf] + r * 68 + kq, mrow + (size_t)r * NN + k0 + kq);
        }
#pragma unroll
        for (int t = 0; t < 8; t++) {          // hp 64x128
            int f = tid + t * 256;
            int k = f >> 5, c = (f & 31) << 2;
            cp16(sB[buf] + k * 132 + c, hpb + (size_t)(k0 + k) * ND + c);
        }
        CP_COMMIT();
    };

    ull acc[8][4];
    zacc8(acc);
    loadChunk(0, 0);
#pragma unroll 1
    for (int c = 0; c < 8; c++) {
        if (c < 7) { loadChunk((c + 1) & 1, (c + 1) * 64); CP_WAIT(1); }
        else       { CP_WAIT(0); }
        __syncthreads();
        mma_half<68>(sA[c & 1], sB[c & 1], 0, r0, c0, acc);
        __syncthreads();
    }
    float* orow = g_neigh + ((size_t)b * NN + row0g) * ND;
#pragma unroll
    for (int i = 0; i < 8; i++) {
        float o[8]; row_f8(acc[i], o);
        float* r = orow + (size_t)(r0 + i) * ND;
        *(float4*)(r + c0)      = make_float4(o[0], o[1], o[2], o[3]);
        *(float4*)(r + c0 + 64) = make_float4(o[4], o[5], o[6], o[7]);
    }
}

// ---------------------------------------------------------------------------
// Kernel 3: fused GRU step, 64 nodes/CTA, 4xtf32 for all 7 GEMMs.
// Gates use folded constants c_g (bias + 512*Wg@Wp_b). Weight K-halves
// (hi/lo, [128][64] -> [128][68]) double-buffered via cp.async.
// ---------------------------------------------------------------------------
#define GRU_SMEM ((2 * 64 * 132 + 4 * 128 * 68) * 4)   // 206848
__global__ void __launch_bounds__(256) gru_t(const float* __restrict__ h_in,
                                             float* __restrict__ h_out,
                                             int do_hp) {
    extern __shared__ float sm[];
    float* sN  = sm;                        // [64][132] agg -> rh -> h'
    float* sH  = sm + 64 * 132;             // [64][132] fp32 h
    float* Wh0 = sm + 2 * 64 * 132;         // [128][68]
    float* Wl0 = Wh0 + 128 * 68;
    float* Wh1 = Wl0 + 128 * 68;
    float* Wl1 = Wh1 + 128 * 68;
    int tid = threadIdx.x, wid = tid >> 5, lane = tid & 31;
    int node0 = blockIdx.x * 64;
    int gm = (wid & 1) * 32, gn = (wid >> 1) * 32;     // 64 nodes x 128 feats

    auto pf = [&](int i) {                   // prefetch weight-half i; commits
        float* dh = (i & 1) ? Wh1 : Wh0;
        float* dl = (i & 1) ? Wl1 : Wl0;
        const float* bh = g_Whi + (i >> 1) * (ND * ND) + (i & 1) * 64;
        const float* bl = g_Wlo + (i >> 1) * (ND * ND) + (i & 1) * 64;
#pragma unroll
        for (int t = 0; t < 8; t++) {
            int f = tid + t * 256; int j = f >> 4, c = (f & 15) << 2;
            cp16(dh + j * 68 + c, bh + (size_t)j * ND + c);
            cp16(dl + j * 68 + c, bl + (size_t)j * ND + c);
        }
        CP_COMMIT();
    };

#pragma unroll
    for (int t = 0; t < 8; t++) {
        int f = tid + t * 256; int r = f >> 5, c = (f & 31) << 2;
        cp16(sN + r * 132 + c, g_neigh + (size_t)(node0 + r) * ND + c);
        cp16(sH + r * 132 + c, h_in + (size_t)(node0 + r) * ND + c);
    }
    pf(0); pf(1);                            // groups {0,1} in flight

    float bZ[8], bR[8], bH[8];
#pragma unroll
    for (int nt = 0; nt < 4; nt++)
#pragma unroll
        for (int j = 0; j < 2; j++) {
            int col = gn + nt * 8 + ((lane & 3) << 1) + j;
            bZ[nt * 2 + j] = g_cvec[0 * ND + col];
            bR[nt * 2 + j] = g_cvec[1 * ND + col];
            bH[nt * 2 + j] = g_cvec[2 * ND + col];
        }

    float acc[2][4][4], zf[2][4][4], rhP[2][4][4];

#define GSTEP(i, Aptr, accvar) do { \
        CP_WAIT(1); __syncthreads(); \
        wgemm4<2, 4, 64, 132, 68>((Aptr), ((i) & 1) ? Wh1 : Wh0, \
                                  ((i) & 1) ? Wl1 : Wl0, gm, gn, accvar); \
        __syncthreads(); \
        if ((i) + 2 < 14) pf((i) + 2); \
    } while (0)

    // z = sig(Wz@agg + Uz@h + cz)
    zaccf<2, 4>(acc);
    GSTEP(0, sN, acc); GSTEP(1, sN + 64, acc); GSTEP(2, sH, acc); GSTEP(3, sH + 64, acc);
#pragma unroll
    for (int mt = 0; mt < 2; mt++)
#pragma unroll
        for (int nt = 0; nt < 4; nt++)
#pragma unroll
            for (int e = 0; e < 4; e++)
                zf[mt][nt][e] = sigm(acc[mt][nt][e] + bZ[nt * 2 + (e & 1)]);
    // r = sig(Wr@agg + Ur@h + cr); park rh = r*h
    zaccf<2, 4>(acc);
    GSTEP(4, sN, acc); GSTEP(5, sN + 64, acc); GSTEP(6, sH, acc); GSTEP(7, sH + 64, acc);
#pragma unroll
    for (int mt = 0; mt < 2; mt++)
#pragma unroll
        for (int nt = 0; nt < 4; nt++)
#pragma unroll
            for (int e = 0; e < 4; e++) {
                int row = gm + mt * 16 + (lane >> 2) + ((e >> 1) << 3);
                int col = gn + nt * 8 + ((lane & 3) << 1) + (e & 1);
                float rv = sigm(acc[mt][nt][e] + bR[nt * 2 + (e & 1)]);
                rhP[mt][nt][e] = rv * sH[row * 132 + col];
            }
    // hhat: Wh@agg (last agg reads), stage rh into sN, then Uh@rh
    zaccf<2, 4>(acc);
    GSTEP(8, sN, acc); GSTEP(9, sN + 64, acc);
#pragma unroll
    for (int mt = 0; mt < 2; mt++)
#pragma unroll
        for (int nt = 0; nt < 4; nt++)
#pragma unroll
            for (int e = 0; e < 4; e++) {
                int row = gm + mt * 16 + (lane >> 2) + ((e >> 1) << 3);
                int col = gn + nt * 8 + ((lane & 3) << 1) + (e & 1);
                sN[row * 132 + col] = rhP[mt][nt][e];   // own cell
            }
    GSTEP(10, sN, acc); GSTEP(11, sN + 64, acc);        // entry sync → rh visible
    // combine: h' = h + z*(tanh(acc+ch) - h); write h_out; stage h' in sN
#pragma unroll
    for (int mt = 0; mt < 2; mt++)
#pragma unroll
        for (int nt = 0; nt < 4; nt++)
#pragma unroll
            for (int e = 0; e < 4; e++) {
                int row = gm + mt * 16 + (lane >> 2) + ((e >> 1) << 3);
                int col = gn + nt * 8 + ((lane & 3) << 1) + (e & 1);
                float hh = tanhf(acc[mt][nt][e] + bH[nt * 2 + (e & 1)]);
                float h = sH[row * 132 + col];
                float hn = fmaf(zf[mt][nt][e], hh - h, h);
                h_out[(size_t)(node0 + row) * ND + col] = hn;
                sN[row * 132 + col] = hn;
            }
    if (do_hp) {
        // hp = h' @ Wp^T  (A = h' on-fly, B = Wp halves) -> g_hp [node][feat]
        float accP[2][4][4]; zaccf<2, 4>(accP);
        CP_WAIT(1); __syncthreads();          // Wp half0 (group 12) + h' visible
        wgemm4<2, 4, 64, 132, 68>(sN, Wh0, Wl0, gm, gn, accP);
        CP_WAIT(0); __syncthreads();          // Wp half1 (group 13)
        wgemm4<2, 4, 64, 132, 68>(sN + 64, Wh1, Wl1, gm, gn, accP);
#pragma unroll
        for (int mt = 0; mt < 2; mt++)
#pragma unroll
            for (int nt = 0; nt < 4; nt++)
#pragma unroll
                for (int e = 0; e < 4; e++) {
                    int row = gm + mt * 16 + (lane >> 2) + ((e >> 1) << 3);
                    int col = gn + nt * 8 + ((lane & 3) << 1) + (e & 1);
                    g_hp[(size_t)(node0 + row) * ND + col] = accP[mt][nt][e];
                }
    } else {
        CP_WAIT(0);                           // drain ledger
    }
#undef GSTEP
}

// ---------------------------------------------------------------------------
extern "C" void kernel_launch(void* const* d_in, const int* in_sizes, int n_in,
                              void* d_out, int out_size) {
    const float* init_node = (const float*)d_in[0];
    const float* mask      = (const float*)d_in[1];
    // d_in[2] = n_steps (fixed = 5)
    const float* Wp_w = (const float*)d_in[3];
    const float* Wp_b = (const float*)d_in[4];
    const float* Wz_w = (const float*)d_in[5];
    const float* Wz_b = (const float*)d_in[6];
    const float* Uz_w = (const float*)d_in[7];
    const float* Uz_b = (const float*)d_in[8];
    const float* Wr_w = (const float*)d_in[9];
    const float* Wr_b = (const float*)d_in[10];
    const float* Ur_w = (const float*)d_in[11];
    const float* Ur_b = (const float*)d_in[12];
    const float* Wh_w = (const float*)d_in[13];
    const float* Wh_b = (const float*)d_in[14];
    const float* Uh_w = (const float*)d_in[15];
    const float* Uh_b = (const float*)d_in[16];
    float* hout = (float*)d_out;

    cudaFuncSetAttribute(xw_t,            cudaFuncAttributeMaxDynamicSharedMemorySize, XW_SMEM);
    cudaFuncSetAttribute(maskgemm_kernel, cudaFuncAttributeMaxDynamicSharedMemorySize, MG_SMEM);
    cudaFuncSetAttribute(gru_t,           cudaFuncAttributeMaxDynamicSharedMemorySize, GRU_SMEM);

    prep_kernel<<<10, 128>>>(Wz_w, Uz_w, Wr_w, Ur_w, Wh_w, Uh_w, Wp_w,
                             Wz_b, Uz_b, Wr_b, Ur_b, Wh_b, Uh_b, Wp_b);
    xw_t<<<NROWS / 64, 256, XW_SMEM>>>(init_node);

    for (int s = 0; s < NSTEPS; s++) {
        maskgemm_kernel<<<dim3(NN / 128, NB), 256, MG_SMEM>>>(mask);
        gru_t<<<NROWS / 64, 256, GRU_SMEM>>>(
            (s == 0) ? init_node : hout, hout, (s < NSTEPS - 1) ? 1 : 0);
    }
}

// round 13
// speedup vs baseline: 1.0868x; 1.0868x over previous
#include <cuda_runtime.h>
#include <cstdint>

// Problem constants (fixed by setup_inputs): B=96, N_NODE=512, D=128, n_steps=5
#define NB 96
#define NN 512
#define ND 128
#define NROWS (NB * NN)            // 49152
#define NSTEPS 5

// Scratch (allocation-free rule: __device__ globals)
// g_W2: weights pair-packed: [w][k2][c][2] with value = W[c][2*k2+p]
__device__ float g_W2[7 * ND * ND];
// g_hp: pair-packed over node j: element (b, j, f) at ((b*256 + j/2)*256 + f*2 + (j&1))
__device__ float g_hp[(size_t)NB * 256 * 256];
__device__ float g_neigh[(size_t)NROWS * ND];   // normal [node][feat]
// weight order: 0=Wz 1=Uz 2=Wr 3=Ur 4=Wh 5=Uh 6=Wp

typedef unsigned long long ull;

__device__ __forceinline__ void fma2(ull& d, ull a, ull b) {
    asm("fma.rn.f32x2 %0, %1, %2, %0;" : "+l"(d) : "l"(a), "l"(b));
}
__device__ __forceinline__ void unpack2(ull v, float& lo, float& hi) {
    asm("mov.b64 {%0,%1}, %2;" : "=f"(lo), "=f"(hi) : "l"(v));
}
__device__ __forceinline__ float accval(ull v) {
    float lo, hi; unpack2(v, lo, hi); return lo + hi;
}
__device__ __forceinline__ float sigmoidf_(float x) { return 1.0f / (1.0f + __expf(-x)); }
__device__ __forceinline__ uint32_t s2u(const void* p) {
    uint32_t a;
    asm("{ .reg .u64 t; cvta.to.shared.u64 t, %1; cvt.u32.u64 %0, t; }" : "=r"(a) : "l"(p));
    return a;
}
__device__ __forceinline__ void cp16(float* dst, const float* src) {
    asm volatile("cp.async.cg.shared.global [%0], [%1], 16;" :: "r"(s2u(dst)), "l"(src));
}
#define CP_COMMIT() asm volatile("cp.async.commit_group;")
#define CP_WAIT(n)  asm volatile("cp.async.wait_group %0;" :: "n"(n))

// thread col for sub-index j (0..7): c = 2*tx + 32*(j>>1) + (j&1)
__device__ __forceinline__ int c_of(int tx, int j) { return 2 * tx + ((j >> 1) << 5) + (j & 1); }

// ---------------------------------------------------------------------------
// K-paired micro-kernel: thread computes 4 rows x 8 cols. acc[r][j] is an
// f32x2 pair accumulating even-k (lo) and odd-k (hi) partial sums.
// sX: [rows][LDA] fp32 k-contig (A pairs = natural LDS.128 halves).
// sW: pair layout, row k2 = 256 floats = 128 col-pairs (w[2k2][c], w[2k2+1][c]).
// Cols per thread: 2tx,2tx+1, +32, +64, +96 — W loads are 16 consecutive
// 16B lanes per phase: conflict-free. A loads broadcast (2 addrs/warp).
// ---------------------------------------------------------------------------
template <int LDA, int KTOT>
__device__ __forceinline__ void mma_pair(const float* __restrict__ sX,
                                         const float* __restrict__ sW,
                                         int r0, int tx, ull acc[4][8]) {
#pragma unroll 2
    for (int kq = 0; kq < KTOT / 4; kq++) {
        ulonglong2 av[4];
#pragma unroll
        for (int i = 0; i < 4; i++)
            av[i] = *(const ulonglong2*)(sX + (r0 + i) * LDA + kq * 4);
#pragma unroll
        for (int h = 0; h < 2; h++) {
            const float* wr = sW + (kq * 2 + h) * 256;
            ulonglong2 w0 = *(const ulonglong2*)(wr + 4 * tx);
            ulonglong2 w1 = *(const ulonglong2*)(wr + 4 * tx + 64);
            ulonglong2 w2 = *(const ulonglong2*)(wr + 4 * tx + 128);
            ulonglong2 w3 = *(const ulonglong2*)(wr + 4 * tx + 192);
#pragma unroll
            for (int i = 0; i < 4; i++) {
                ull ap = h ? av[i].y : av[i].x;
                fma2(acc[i][0], ap, w0.x); fma2(acc[i][1], ap, w0.y);
                fma2(acc[i][2], ap, w1.x); fma2(acc[i][3], ap, w1.y);
                fma2(acc[i][4], ap, w2.x); fma2(acc[i][5], ap, w2.y);
                fma2(acc[i][6], ap, w3.x); fma2(acc[i][7], ap, w3.y);
            }
        }
    }
}
__device__ __forceinline__ void zacc(ull acc[4][8]) {
#pragma unroll
    for (int i = 0; i < 4; i++)
#pragma unroll
        for (int j = 0; j < 8; j++) acc[i][j] = 0ull;
}

// ---------------------------------------------------------------------------
// Kernel 0: pair-pack the 7 weights: g_W2[w][k2*256 + c*2 + p] = W[c][2k2+p]
// ---------------------------------------------------------------------------
__global__ void prep_kernel(const float* __restrict__ Wz, const float* __restrict__ Uz,
                            const float* __restrict__ Wr, const float* __restrict__ Ur,
                            const float* __restrict__ Wh, const float* __restrict__ Uh,
                            const float* __restrict__ Wp) {
    const float* src = (blockIdx.x == 0) ? Wz : (blockIdx.x == 1) ? Uz :
                       (blockIdx.x == 2) ? Wr : (blockIdx.x == 3) ? Ur :
                       (blockIdx.x == 4) ? Wh : (blockIdx.x == 5) ? Uh : Wp;
    float* dst = g_W2 + blockIdx.x * (ND * ND);
    for (int idx = threadIdx.x; idx < ND * ND; idx += blockDim.x) {
        int k2 = idx >> 8, c = (idx >> 1) & 127, p = idx & 1;
        dst[idx] = src[c * ND + 2 * k2 + p];
    }
}

// ---------------------------------------------------------------------------
// Kernel 1 (once): hp0 = init_node @ Wp^T, written pair-packed.
// 256 thr, 64-node tiles (grid 768).
// ---------------------------------------------------------------------------
#define XW_SMEM ((64 * 128 + 128 * 128) * 4)   // 98304
__global__ void __launch_bounds__(256) xw_kernel(const float* __restrict__ X) {
    extern __shared__ float sm[];
    float* sX = sm;                 // [64][128]
    float* sW = sm + 64 * 128;      // pair layout, 16384 floats
    int tid = threadIdx.x;
    int tx = tid & 15, ty = tid >> 4;
    int r0 = ty * 4;
    long base = (long)blockIdx.x * 64;
#pragma unroll
    for (int t = 0; t < 8; t++) {
        int f = tid + t * 256; int r = f >> 5, c = (f & 31) << 2;
        cp16(sX + r * 128 + c, X + (base + r) * ND + c);
    }
#pragma unroll
    for (int t = 0; t < 16; t++) {
        int f = tid + t * 256;
        cp16(sW + f * 4, g_W2 + 6 * ND * ND + f * 4);
    }
    CP_COMMIT();
    CP_WAIT(0); __syncthreads();
    ull acc[4][8];
    zacc(acc);
    mma_pair<128, 128>(sX, sW, r0, tx, acc);
#pragma unroll
    for (int i = 0; i < 4; i++) {
        long g = base + r0 + i;
        int b = (int)(g >> 9), j = (int)(g & 511);
        float* dst = g_hp + ((size_t)b * 256 + (j >> 1)) * 256 + (j & 1);
#pragma unroll
        for (int jj = 0; jj < 8; jj++)
            dst[c_of(tx, jj) * 2] = accval(acc[i][jj]);
    }
}

// ---------------------------------------------------------------------------
// Kernel 2: neigh[b] = mask[b] @ hp[b] + 512*Wp_b. 64-row tiles, grid (8,96),
// 256 thr, K=512 in 8 chunks of 64 j, cp.async double-buffered.
// A = mask (natural pairs over j); W-role = hp pair-packed (direct cp.async).
// ---------------------------------------------------------------------------
#define MG_SMEM ((2 * 64 * 64 + 2 * 32 * 256) * 4)   // 98304 -> 2 CTA/SM
__global__ void __launch_bounds__(256) maskgemm_kernel(const float* __restrict__ mask,
                                                       const float* __restrict__ bp) {
    extern __shared__ float sm[];
    float* sA[2] = { sm, sm + 64 * 64 };
    float* sB[2] = { sm + 2 * 64 * 64, sm + 2 * 64 * 64 + 32 * 256 };
    int b = blockIdx.y;
    int row0g = blockIdx.x * 64;
    int tid = threadIdx.x;
    int tx = tid & 15, ty = tid >> 4;
    int r0 = ty * 4;
    const float* mrow = mask + ((size_t)b * NN + row0g) * NN;
    const float* hpb  = g_hp + (size_t)b * 256 * 256;

    float bj[8];
#pragma unroll
    for (int j = 0; j < 8; j++) bj[j] = 512.0f * __ldg(bp + c_of(tx, j));

    auto loadChunk = [&](int buf, int c) {
#pragma unroll
        for (int t = 0; t < 4; t++) {          // mask 64x64: 1024 f4
            int f = tid + t * 256;
            int r = f >> 4, kq = (f & 15) << 2;
            cp16(sA[buf] + r * 64 + kq, mrow + (size_t)r * NN + c * 64 + kq);
        }
#pragma unroll
        for (int t = 0; t < 8; t++) {          // hp paired chunk: 32 j2 x 256
            int f = tid + t * 256;
            int j2r = f >> 6, off = (f & 63) << 2;
            cp16(sB[buf] + j2r * 256 + off, hpb + (size_t)(c * 32 + j2r) * 256 + off);
        }
        CP_COMMIT();
    };

    ull acc[4][8];
    zacc(acc);
    loadChunk(0, 0);
#pragma unroll 1
    for (int c = 0; c < 8; c++) {
        if (c < 7) { loadChunk((c + 1) & 1, c + 1); CP_WAIT(1); }
        else       { CP_WAIT(0); }
        __syncthreads();
        mma_pair<64, 64>(sA[c & 1], sB[c & 1], r0, tx, acc);
        __syncthreads();
    }
    float* orow = g_neigh + ((size_t)b * NN + row0g) * ND;
#pragma unroll
    for (int i = 0; i < 4; i++) {
        float* r = orow + (size_t)(r0 + i) * ND;
#pragma unroll
        for (int g = 0; g < 4; g++) {
            float2 v;
            v.x = accval(acc[i][g * 2 + 0]) + bj[g * 2 + 0];
            v.y = accval(acc[i][g * 2 + 1]) + bj[g * 2 + 1];
            *(float2*)(r + 2 * tx + 32 * g) = v;
        }
    }
}

// ---------------------------------------------------------------------------
// Kernel 3: fused GRU, 64 nodes/CTA, K-paired fp32, full-weight double buffer.
// smem: sN[64][128] (neigh->h'), sH (h), sRH (r*h), W0/W1 pair (64KB each).
// ---------------------------------------------------------------------------
#define GRU_SMEM ((3 * 64 * 128 + 2 * 128 * 128 + 3 * 128) * 4)   // 230912
__global__ void __launch_bounds__(256) gru_kernel(const float* __restrict__ h_in,
                                                  float* __restrict__ h_out,
                                                  const float* __restrict__ Wz_b, const float* __restrict__ Uz_b,
                                                  const float* __restrict__ Wr_b, const float* __restrict__ Ur_b,
                                                  const float* __restrict__ Wh_b, const float* __restrict__ Uh_b,
                                                  int do_hp) {
    extern __shared__ float sm[];
    float* sN  = sm;                        // [64][128]
    float* sH  = sN + 64 * 128;
    float* sRH = sH + 64 * 128;
    float* W0  = sRH + 64 * 128;            // 16384 floats (pair layout)
    float* W1  = W0 + 128 * 128;
    float* sBz = W1 + 128 * 128;            // 128
    float* sBr = sBz + 128;
    float* sBh = sBr + 128;
    int tid = threadIdx.x;
    int tx = tid & 15, ty = tid >> 4;
    int r0 = ty * 4;
    long base = (long)blockIdx.x * 64;

    auto cpw = [&](float* dst, int w) {      // commits a group
#pragma unroll
        for (int t = 0; t < 16; t++) {
            int f = tid + t * 256;
            cp16(dst + f * 4, g_W2 + w * (ND * ND) + f * 4);
        }
        CP_COMMIT();
    };

    // G_A = {sN, sH, W0=Wz}; G_B = {W1=Uz}
#pragma unroll
    for (int t = 0; t < 8; t++) {
        int f = tid + t * 256; int r = f >> 5, c = (f & 31) << 2;
        cp16(sN + r * 128 + c, g_neigh + (base + r) * ND + c);
        cp16(sH + r * 128 + c, h_in + (base + r) * ND + c);
    }
#pragma unroll
    for (int t = 0; t < 16; t++) {
        int f = tid + t * 256;
        cp16(W0 + f * 4, g_W2 + 0 * (ND * ND) + f * 4);
    }
    CP_COMMIT();                             // G_A
    cpw(W1, 1);                              // G_B = Uz
    if (tid < 128) {
        sBz[tid] = Wz_b[tid] + Uz_b[tid];
        sBr[tid] = Wr_b[tid] + Ur_b[tid];
        sBh[tid] = Wh_b[tid] + Uh_b[tid];
    }

    ull acc[4][8];
    float zf[4][8];

    CP_WAIT(1); __syncthreads();             // G_A ready (+bias fenced)
    zacc(acc);
    mma_pair<128, 128>(sN, W0, r0, tx, acc);             // z1 = neigh@Wz
    __syncthreads(); cpw(W0, 2);                         // G_C = Wr
    CP_WAIT(1); __syncthreads();             // G_B: Uz
    mma_pair<128, 128>(sH, W1, r0, tx, acc);             // z2 += h@Uz
#pragma unroll
    for (int i = 0; i < 4; i++)
#pragma unroll
        for (int j = 0; j < 8; j++)
            zf[i][j] = sigmoidf_(accval(acc[i][j]) + sBz[c_of(tx, j)]);
    __syncthreads(); cpw(W1, 3);                         // G_D = Ur
    CP_WAIT(1); __syncthreads();             // G_C: Wr
    zacc(acc);
    mma_pair<128, 128>(sN, W0, r0, tx, acc);             // r1 = neigh@Wr
    __syncthreads(); cpw(W0, 4);                         // G_E = Wh
    CP_WAIT(1); __syncthreads();             // G_D: Ur
    mma_pair<128, 128>(sH, W1, r0, tx, acc);             // r2 += h@Ur
#pragma unroll
    for (int i = 0; i < 4; i++)                          // rh = sig(r)*h -> sRH
#pragma unroll
        for (int j = 0; j < 8; j++) {
            int c = c_of(tx, j);
            float rv = sigmoidf_(accval(acc[i][j]) + sBr[c]);
            sRH[(r0 + i) * 128 + c] = rv * sH[(r0 + i) * 128 + c];
        }
    __syncthreads(); cpw(W1, 5);                         // G_F = Uh (sync fences rh)
    CP_WAIT(1); __syncthreads();             // G_E: Wh
    zacc(acc);
    mma_pair<128, 128>(sN, W0, r0, tx, acc);             // h1 = neigh@Wh (last sN read)
    __syncthreads(); cpw(W0, 6);                         // G_G = Wp
    CP_WAIT(1); __syncthreads();             // G_F: Uh (rh visible)
    mma_pair<128, 128>(sRH, W1, r0, tx, acc);            // h2 += rh@Uh
    // combine (no sync needed: sN writes are own cells; others read sRH/W1 only)
#pragma unroll
    for (int i = 0; i < 4; i++) {
        float* horow = h_out + (base + r0 + i) * ND;
#pragma unroll
        for (int g = 0; g < 4; g++) {
            float2 v;
#pragma unroll
            for (int p = 0; p < 2; p++) {
                int j = g * 2 + p;
                int c = c_of(tx, j);
                float hh = tanhf(accval(acc[i][j]) + sBh[c]);
                float h = sH[(r0 + i) * 128 + c];
                float hn = fmaf(zf[i][j], hh - h, h);
                sN[(r0 + i) * 128 + c] = hn;             // stage h'
                (p == 0) ? (v.x = hn) : (v.y = hn);
            }
            *(float2*)(horow + 2 * tx + 32 * g) = v;
        }
    }
    if (do_hp) {
        CP_WAIT(0); __syncthreads();         // G_G: Wp ready + h' visible
        zacc(acc);
        mma_pair<128, 128>(sN, W0, r0, tx, acc);         // hp = h'@Wp^T
#pragma unroll
        for (int i = 0; i < 4; i++) {
            long g = base + r0 + i;
            int b = (int)(g >> 9), j = (int)(g & 511);
            float* dst = g_hp + ((size_t)b * 256 + (j >> 1)) * 256 + (j & 1);
#pragma unroll
            for (int jj = 0; jj < 8; jj++)
                dst[c_of(tx, jj) * 2] = accval(acc[i][jj]);
        }
    } else {
        CP_WAIT(0);                          // drain ledger
    }
}

// ---------------------------------------------------------------------------
extern "C" void kernel_launch(void* const* d_in, const int* in_sizes, int n_in,
                              void* d_out, int out_size) {
    const float* init_node = (const float*)d_in[0];
    const float* mask      = (const float*)d_in[1];
    // d_in[2] = n_steps (fixed at 5 by the problem definition)
    const float* Wp_w = (const float*)d_in[3];
    const float* Wp_b = (const float*)d_in[4];
    const float* Wz_w = (const float*)d_in[5];
    const float* Wz_b = (const float*)d_in[6];
    const float* Uz_w = (const float*)d_in[7];
    const float* Uz_b = (const float*)d_in[8];
    const float* Wr_w = (const float*)d_in[9];
    const float* Wr_b = (const float*)d_in[10];
    const float* Ur_w = (const float*)d_in[11];
    const float* Ur_b = (const float*)d_in[12];
    const float* Wh_w = (const float*)d_in[13];
    const float* Wh_b = (const float*)d_in[14];
    const float* Uh_w = (const float*)d_in[15];
    const float* Uh_b = (const float*)d_in[16];
    float* hout = (float*)d_out;

    cudaFuncSetAttribute(gru_kernel,      cudaFuncAttributeMaxDynamicSharedMemorySize, GRU_SMEM);
    cudaFuncSetAttribute(xw_kernel,       cudaFuncAttributeMaxDynamicSharedMemorySize, XW_SMEM);
    cudaFuncSetAttribute(maskgemm_kernel, cudaFuncAttributeMaxDynamicSharedMemorySize, MG_SMEM);

    prep_kernel<<<7, 256>>>(Wz_w, Uz_w, Wr_w, Ur_w, Wh_w, Uh_w, Wp_w);
    xw_kernel<<<NROWS / 64, 256, XW_SMEM>>>(init_node);

    for (int s = 0; s < NSTEPS; s++) {
        maskgemm_kernel<<<dim3(NN / 64, NB), 256, MG_SMEM>>>(mask, Wp_b);
        gru_kernel<<<NROWS / 64, 256, GRU_SMEM>>>(
            (s == 0) ? init_node : hout, hout,
            Wz_b, Uz_b, Wr_b, Ur_b, Wh_b, Uh_b, (s < NSTEPS - 1) ? 1 : 0);
    }
}